// round 5
// baseline (speedup 1.0000x reference)
#include <cuda_runtime.h>
#include <math.h>

#define BB 32
#define DIN 1024
#define DOUT 1024
#define BETA 0.9f
#define LEAK 0.9f

#define KTILE 32
#define NSPLIT (DIN / KTILE)   /* 32 */
#define JTILE 128
#define NJT (DOUT / JTILE)     /* 8 */
#define BSPLIT 4
#define BQ (BB / BSPLIT)       /* 8 */

/* output offsets (floats), in reference return order:
   s, E_W2, E_b2, Rh_W2, Rh_b2, g_bar2, r2 */
#define OFF_S  0
#define OFF_EW (BB * DOUT)
#define OFF_EB (OFF_EW + BB * DIN * DOUT)
#define OFF_RW (OFF_EB + BB * DOUT)
#define OFF_RB (OFF_RW + BB * DIN * DOUT)
#define OFF_G  (OFF_RB + BB * DOUT)
#define OFF_R  (OFF_G + BB * DOUT)

__device__ float g_hpart[NSPLIT][BB * DOUT];     /* 4 MB scratch, fully rewritten every call */

/* ---------------- kernel 1: split-K GEMM, h partials ------------------- */
/* grid (NJT=8, NSPLIT=32, BSPLIT=4) = 1024 blocks, 128 threads. Each thread
   owns one j column and 8 batch accumulators; 32 independent W loads per
   thread for deep MLP; x tile in smem. The 4 b-blocks sharing (jt,ks) hit
   the same W lines in L2. */
__global__ void __launch_bounds__(128) gemm_partial(const float* __restrict__ x,
                                                    const float* __restrict__ W) {
    __shared__ float xs[BQ][KTILE];              /* 1 KB */
    const int jt  = blockIdx.x;
    const int ks  = blockIdx.y;
    const int bs  = blockIdx.z;
    const int tid = threadIdx.x;
    const int j   = jt * JTILE + tid;
    const int k0  = ks * KTILE;
    const int b0  = bs * BQ;

    /* 256 smem elements, 2 per thread */
    {
        int bb = tid >> 5, kk = tid & 31;
        xs[bb][kk] = x[(b0 + bb) * DIN + k0 + kk];
        int t2 = tid + 128;
        int bb2 = t2 >> 5, kk2 = t2 & 31;
        xs[bb2][kk2] = x[(b0 + bb2) * DIN + k0 + kk2];
    }
    __syncthreads();

    float acc[BQ];
#pragma unroll
    for (int bb = 0; bb < BQ; bb++) acc[bb] = 0.0f;

#pragma unroll
    for (int kk = 0; kk < KTILE; kk += 4) {
        const float w0 = W[(k0 + kk + 0) * DOUT + j];
        const float w1 = W[(k0 + kk + 1) * DOUT + j];
        const float w2 = W[(k0 + kk + 2) * DOUT + j];
        const float w3 = W[(k0 + kk + 3) * DOUT + j];
#pragma unroll
        for (int bb = 0; bb < BQ; bb++) {
            float4 xv = *(const float4*)&xs[bb][kk];
            acc[bb] = fmaf(xv.x, w0, acc[bb]);
            acc[bb] = fmaf(xv.y, w1, acc[bb]);
            acc[bb] = fmaf(xv.z, w2, acc[bb]);
            acc[bb] = fmaf(xv.w, w3, acc[bb]);
        }
    }

#pragma unroll
    for (int bb = 0; bb < BQ; bb++)
        g_hpart[ks][(b0 + bb) * DOUT + j] = acc[bb];
}

/* ---------------- kernel 2: activation + all small outputs ------------- */
/* float4 over j: 8192 threads, each produces 4 outputs. */
__global__ void __launch_bounds__(256) act_small(const float4* __restrict__ bias4,
                                                 const float4* __restrict__ u4,
                                                 const float4* __restrict__ E_b4,
                                                 const float4* __restrict__ Rh_b4,
                                                 const float4* __restrict__ g_bar4,
                                                 const float* __restrict__ r,
                                                 float* __restrict__ out) {
    const int idx4 = blockIdx.x * 256 + threadIdx.x;   /* 0..8191 */
    const int bb = idx4 >> 8;                           /* / (DOUT/4) */
    const int j4 = idx4 & 255;

    float4 h = bias4[j4];
#pragma unroll
    for (int ks = 0; ks < NSPLIT; ks++) {
        const float4 p = ((const float4*)g_hpart[ks])[idx4];
        h.x += p.x; h.y += p.y; h.z += p.z; h.w += p.w;
    }

    const float4 uu = u4[idx4];
    const float4 eb = E_b4[idx4];
    const float4 rb = Rh_b4[idx4];
    const float4 gb = g_bar4[idx4];

    const float ratio0 = LEAK * r[bb];
    const float r2 = ratio0 + 1.0f;
    const float ratio = ratio0 / r2;

    float4 so, ebo, rbo, go;

    {
        const float un = BETA * uu.x + h.x;
        const float s  = 1.0f / (1.0f + expf(-(un - 1.0f)));
        const float sg = s * (1.0f - s);
        const float a  = BETA * sg;
        so.x = s;
        const float eb1 = BETA * eb.x + 1.0f;
        ebo.x = BETA * eb1 + 1.0f;
        rbo.x = a * rb.x + (a * eb1 + sg);
        go.x  = ratio * gb.x + (1.0f - ratio) * a;
    }
    {
        const float un = BETA * uu.y + h.y;
        const float s  = 1.0f / (1.0f + expf(-(un - 1.0f)));
        const float sg = s * (1.0f - s);
        const float a  = BETA * sg;
        so.y = s;
        const float eb1 = BETA * eb.y + 1.0f;
        ebo.y = BETA * eb1 + 1.0f;
        rbo.y = a * rb.y + (a * eb1 + sg);
        go.y  = ratio * gb.y + (1.0f - ratio) * a;
    }
    {
        const float un = BETA * uu.z + h.z;
        const float s  = 1.0f / (1.0f + expf(-(un - 1.0f)));
        const float sg = s * (1.0f - s);
        const float a  = BETA * sg;
        so.z = s;
        const float eb1 = BETA * eb.z + 1.0f;
        ebo.z = BETA * eb1 + 1.0f;
        rbo.z = a * rb.z + (a * eb1 + sg);
        go.z  = ratio * gb.z + (1.0f - ratio) * a;
    }
    {
        const float un = BETA * uu.w + h.w;
        const float s  = 1.0f / (1.0f + expf(-(un - 1.0f)));
        const float sg = s * (1.0f - s);
        const float a  = BETA * sg;
        so.w = s;
        const float eb1 = BETA * eb.w + 1.0f;
        ebo.w = BETA * eb1 + 1.0f;
        rbo.w = a * rb.w + (a * eb1 + sg);
        go.w  = ratio * gb.w + (1.0f - ratio) * a;
    }

    ((float4*)(out + OFF_S))[idx4]  = so;
    ((float4*)(out + OFF_EB))[idx4] = ebo;
    ((float4*)(out + OFF_RB))[idx4] = rbo;
    ((float4*)(out + OFF_G))[idx4]  = go;
    if (j4 == 0) out[OFF_R + bb] = r2;
}

/* ---------------- kernel 3: big streaming trace update ----------------- */
/* Unroll x2: each thread handles two float4s 4M apart -> 4 independent 16B
   stream loads in flight before any math. Streaming hints keep the 512 MB
   from churning L2. */
#define NVEC (BB * DIN * DOUT / 4)       /* 8388608 */
#define HVEC (NVEC / 2)                  /* 4194304 */

__device__ __forceinline__ void trace4(const float4 ew, const float4 rh,
                                       const float4 s4, const float xv,
                                       float4& o1, float4& o2) {
    {
        const float sg = s4.x * (1.0f - s4.x);
        const float a  = BETA * sg;
        const float e1 = fmaf(BETA, ew.x, xv);
        o1.x = fmaf(BETA, e1, xv);
        o2.x = fmaf(a, rh.x, fmaf(a, e1, xv * sg));
    }
    {
        const float sg = s4.y * (1.0f - s4.y);
        const float a  = BETA * sg;
        const float e1 = fmaf(BETA, ew.y, xv);
        o1.y = fmaf(BETA, e1, xv);
        o2.y = fmaf(a, rh.y, fmaf(a, e1, xv * sg));
    }
    {
        const float sg = s4.z * (1.0f - s4.z);
        const float a  = BETA * sg;
        const float e1 = fmaf(BETA, ew.z, xv);
        o1.z = fmaf(BETA, e1, xv);
        o2.z = fmaf(a, rh.z, fmaf(a, e1, xv * sg));
    }
    {
        const float sg = s4.w * (1.0f - s4.w);
        const float a  = BETA * sg;
        const float e1 = fmaf(BETA, ew.w, xv);
        o1.w = fmaf(BETA, e1, xv);
        o2.w = fmaf(a, rh.w, fmaf(a, e1, xv * sg));
    }
}

__global__ void __launch_bounds__(256) big_update(const float* __restrict__ x,
                                                  const float4* __restrict__ E_W,
                                                  const float4* __restrict__ Rh_W,
                                                  float* __restrict__ out) {
    const float4* __restrict__ s4p = (const float4*)(out + OFF_S);
    float4* __restrict__ ew2 = (float4*)(out + OFF_EW);
    float4* __restrict__ rw2 = (float4*)(out + OFF_RW);

    const int idx0 = blockIdx.x * 256 + threadIdx.x;   /* 0..HVEC-1 */
    const int idx1 = idx0 + HVEC;

    /* all four DRAM stream loads issued before any dependent math */
    const float4 ew0 = __ldcs(&E_W[idx0]);
    const float4 rh0 = __ldcs(&Rh_W[idx0]);
    const float4 ew1 = __ldcs(&E_W[idx1]);
    const float4 rh1 = __ldcs(&Rh_W[idx1]);

    const int bb0 = idx0 >> 18;
    const int rem0 = idx0 & 262143;
    const int i0 = rem0 >> 8;
    const int j40 = rem0 & 255;
    const int bb1 = idx1 >> 18;
    const int rem1 = idx1 & 262143;
    const int i1 = rem1 >> 8;
    const int j41 = rem1 & 255;

    const float  xv0 = __ldg(&x[bb0 * DIN + i0]);
    const float4 s40 = s4p[bb0 * 256 + j40];
    const float  xv1 = __ldg(&x[bb1 * DIN + i1]);
    const float4 s41 = s4p[bb1 * 256 + j41];

    float4 o1a, o2a, o1b, o2b;
    trace4(ew0, rh0, s40, xv0, o1a, o2a);
    trace4(ew1, rh1, s41, xv1, o1b, o2b);

    __stcs(&ew2[idx0], o1a);
    __stcs(&rw2[idx0], o2a);
    __stcs(&ew2[idx1], o1b);
    __stcs(&rw2[idx1], o2b);
}

extern "C" void kernel_launch(void* const* d_in, const int* in_sizes, int n_in,
                              void* d_out, int out_size) {
    const float* x     = (const float*)d_in[0];
    const float* W     = (const float*)d_in[1];
    const float* bias  = (const float*)d_in[2];
    const float* u     = (const float*)d_in[3];
    const float* E_W   = (const float*)d_in[4];
    const float* E_b   = (const float*)d_in[5];
    const float* Rh_W  = (const float*)d_in[6];
    const float* Rh_b  = (const float*)d_in[7];
    const float* g_bar = (const float*)d_in[8];
    const float* r     = (const float*)d_in[9];
    float* out = (float*)d_out;

    dim3 gg(NJT, NSPLIT, BSPLIT);
    gemm_partial<<<gg, 128>>>(x, W);
    act_small<<<BB * DOUT / 4 / 256, 256>>>((const float4*)bias, (const float4*)u,
                                            (const float4*)E_b, (const float4*)Rh_b,
                                            (const float4*)g_bar, r, out);
    big_update<<<HVEC / 256, 256>>>(x, (const float4*)E_W, (const float4*)Rh_W, out);
}